// round 5
// baseline (speedup 1.0000x reference)
#include <cuda_runtime.h>
#include <cuda_bf16.h>
#include <cstdint>

// ---------------------------------------------------------------------------
// Problem constants
constexpr int B_   = 4;
constexpr int G_   = 8;
constexpr int NH_  = 8;
constexpr int DIM_ = 256;    // HID / G
constexpr int S_   = 4096;
constexpr int SPAD = 4104;   // padded K/V time pitch (S_+1, rounded to 8)
constexpr int HID_ = 2048;
constexpr int KP   = 768;    // stacked K for A operand (3 x 256: hi|lo|hi)

// ---------------------------------------------------------------------------
// Scratch (device globals; allocation is forbidden)
__device__ float g_Q[(size_t)B_ * G_ * DIM_ * S_];    // (bg, c, s)
__device__ float g_K[(size_t)B_ * G_ * DIM_ * SPAD];  // (bg, c, t) t in [0,4096]
__device__ float g_V[(size_t)B_ * G_ * DIM_ * SPAD];

// B operands in [bg][512 rows][4096 t]:  rows 0-255 = hi(c), rows 256-511 = lo(c)
__device__ __nv_bfloat16 g_Bx[(size_t)32 * 512 * S_];
__device__ __nv_bfloat16 g_Bo[(size_t)32 * 512 * S_];
__device__ __nv_bfloat16 g_Aq[(size_t)G_ * 768 * KP]; // w_qkv stacked [g][o][hi|lo|hi]
__device__ __nv_bfloat16 g_Ap[(size_t)G_ * 256 * KP]; // w_pred stacked

// ---------------------------------------------------------------------------
__device__ __forceinline__ uint32_t smem_u32(const void* p) {
    uint32_t a;
    asm("{ .reg .u64 t; cvta.to.shared.u64 t, %1; cvt.u32.u64 %0, t; }" : "=r"(a) : "l"(p));
    return a;
}
__device__ __forceinline__ void cp_async16(uint32_t dst, const void* src) {
    asm volatile("cp.async.cg.shared.global [%0], [%1], 16;" :: "r"(dst), "l"(src));
}
__device__ __forceinline__ void ldmatrix_x4(uint32_t* r, uint32_t addr) {
    asm volatile("ldmatrix.sync.aligned.m8n8.x4.shared.b16 {%0,%1,%2,%3}, [%4];"
                 : "=r"(r[0]), "=r"(r[1]), "=r"(r[2]), "=r"(r[3]) : "r"(addr));
}
__device__ __forceinline__ void ldmatrix_x4_trans(uint32_t* r, uint32_t addr) {
    asm volatile("ldmatrix.sync.aligned.m8n8.x4.trans.shared.b16 {%0,%1,%2,%3}, [%4];"
                 : "=r"(r[0]), "=r"(r[1]), "=r"(r[2]), "=r"(r[3]) : "r"(addr));
}
__device__ __forceinline__ void mma16816(float* c, const uint32_t* a, uint32_t b0, uint32_t b1) {
    asm volatile(
        "mma.sync.aligned.m16n8k16.row.col.f32.bf16.bf16.f32 "
        "{%0,%1,%2,%3}, {%4,%5,%6,%7}, {%8,%9}, {%0,%1,%2,%3};"
        : "+f"(c[0]), "+f"(c[1]), "+f"(c[2]), "+f"(c[3])
        : "r"(a[0]), "r"(a[1]), "r"(a[2]), "r"(a[3]), "r"(b0), "r"(b1));
}

// ---------------------------------------------------------------------------
// Weights [R][256] fp32 -> [R][768] bf16 stacked [hi | lo | hi]
// ---------------------------------------------------------------------------
__global__ void convert_w(const float* __restrict__ w, __nv_bfloat16* __restrict__ A,
                          int total) {
    int i = blockIdx.x * 256 + threadIdx.x;
    if (i >= total) return;
    int r = i >> 8, c = i & 255;
    float v = w[i];
    __nv_bfloat16 h = __float2bfloat16(v);
    __nv_bfloat16 l = __float2bfloat16(v - __bfloat162float(h));
    __nv_bfloat16* row = A + (size_t)r * KP;
    row[c] = h;
    row[256 + c] = l;
    row[512 + c] = h;
}

// ---------------------------------------------------------------------------
// x [bg][256 c][4096 t] fp32 -> g_Bx [bg][512][4096] bf16 (row c = hi, 256+c = lo)
// ---------------------------------------------------------------------------
__global__ __launch_bounds__(256)
void convert_x(const float* __restrict__ x, __nv_bfloat16* __restrict__ dst) {
    int i = blockIdx.x * 256 + threadIdx.x;  // over 32*256*1024 float4 slots
    int t4 = (i & 1023) << 2;
    int c  = (i >> 10) & 255;
    int bg = i >> 18;
    float4 v = *reinterpret_cast<const float4*>(x + ((size_t)bg * 256 + c) * S_ + t4);
    __nv_bfloat162 h0, h1, l0, l1;
    h0.x = __float2bfloat16(v.x); h0.y = __float2bfloat16(v.y);
    h1.x = __float2bfloat16(v.z); h1.y = __float2bfloat16(v.w);
    l0.x = __float2bfloat16(v.x - __bfloat162float(h0.x));
    l0.y = __float2bfloat16(v.y - __bfloat162float(h0.y));
    l1.x = __float2bfloat16(v.z - __bfloat162float(h1.x));
    l1.y = __float2bfloat16(v.w - __bfloat162float(h1.y));
    __nv_bfloat162* dh = reinterpret_cast<__nv_bfloat162*>(
        dst + ((size_t)bg * 512 + c) * S_ + t4);
    dh[0] = h0; dh[1] = h1;
    __nv_bfloat162* dl = reinterpret_cast<__nv_bfloat162*>(
        dst + ((size_t)bg * 512 + 256 + c) * S_ + t4);
    dl[0] = l0; dl[1] = l1;
}

// ---------------------------------------------------------------------------
// mma.sync GEMM: D[128 o x 128 t] = A[o][k'768] . B[t][k 512]
// 4-stage cp.async pipeline, ONE __syncthreads per K-chunk.
// ch 0-7: Ah.Bh ; 8-15: Al.Bh ; 16-23: Ah.Bl
// ---------------------------------------------------------------------------
constexpr int NCH = 24;

__global__ __launch_bounds__(256, 2)
void gemm_mma(const __nv_bfloat16* __restrict__ Aall,
              const __nv_bfloat16* __restrict__ Ball,
              const float* __restrict__ bias,
              int Mtot, int mode, float* __restrict__ out) {
    // per stage: A 128(o)x32(k) 8KB (64B rows) + B 32(k)x128(t) 8KB (256B rows)
    extern __shared__ __align__(1024) char sbuf[];  // 4 * 16384
    const int tid  = threadIdx.x;
    const int lane = tid & 31;
    const int wid  = tid >> 5;
    const int wm   = wid & 3;
    const int wn   = wid >> 2;
    const int bg = blockIdx.z, g = bg & 7;
    const int o0 = blockIdx.y * 128, t0 = blockIdx.x * 128;

    const uint32_t sbase = smem_u32(sbuf);
    const __nv_bfloat16* A  = Aall + ((size_t)g * Mtot + o0) * KP;
    const __nv_bfloat16* Bp = Ball + (size_t)bg * 512 * S_;

    auto load_stage = [&](int ch, int st) {
        uint32_t sA = sbase + st * 16384;
        uint32_t sB = sA + 8192;
        const char* a8 = (const char*)A + (size_t)ch * 64;
        int bch = (ch < 8) ? ch : ch - 8;
        const char* b8 = (const char*)(Bp + ((size_t)bch * 32) * S_ + t0);
#pragma unroll
        for (int i = 0; i < 2; i++) {
            int id  = tid + i * 256;
            int ra = id >> 2, ca = id & 3;
            uint32_t offA = ra * 64 + ((ca ^ ((ra >> 1) & 3)) << 4);
            cp_async16(sA + offA, a8 + (size_t)ra * (KP * 2) + ca * 16);
            int rb = id >> 4, cb = id & 15;
            uint32_t offB = rb * 256 + ((cb ^ (rb & 7)) << 4);
            cp_async16(sB + offB, b8 + (size_t)rb * (S_ * 2) + cb * 16);
        }
    };

    float acc[2][8][4];
#pragma unroll
    for (int mi = 0; mi < 2; mi++)
#pragma unroll
        for (int nj = 0; nj < 8; nj++)
#pragma unroll
            for (int q = 0; q < 4; q++) acc[mi][nj][q] = 0.f;

    load_stage(0, 0);
    asm volatile("cp.async.commit_group;" ::: "memory");
    load_stage(1, 1);
    asm volatile("cp.async.commit_group;" ::: "memory");
    load_stage(2, 2);
    asm volatile("cp.async.commit_group;" ::: "memory");

    const int gsel = lane >> 3;
    const int rin  = lane & 7;
    const int bl   = lane & 15;
    const int bh   = lane >> 4;

    for (int ch = 0; ch < NCH; ch++) {
        if (ch < NCH - 3) asm volatile("cp.async.wait_group 2;" ::: "memory");
        else              asm volatile("cp.async.wait_group 0;" ::: "memory");
        __syncthreads();
        if (ch + 3 < NCH) {
            load_stage(ch + 3, (ch + 3) & 3);
            asm volatile("cp.async.commit_group;" ::: "memory");
        }
        uint32_t sA = sbase + (ch & 3) * 16384;
        uint32_t sB = sA + 8192;
#pragma unroll
        for (int kk = 0; kk < 2; kk++) {
            uint32_t afr[2][4];
#pragma unroll
            for (int mi = 0; mi < 2; mi++) {
                int row   = wm * 32 + mi * 16 + (gsel & 1) * 8 + rin;
                int chunk = kk * 2 + (gsel >> 1);
                uint32_t addr = sA + row * 64 + ((chunk ^ ((row >> 1) & 3)) << 4);
                ldmatrix_x4(afr[mi], addr);
            }
            uint32_t bfr[4][4];
#pragma unroll
            for (int nt = 0; nt < 4; nt++) {
                int krow  = kk * 16 + bl;
                int chunk = wn * 8 + nt * 2 + bh;
                uint32_t addr = sB + krow * 256 + ((chunk ^ (krow & 7)) << 4);
                ldmatrix_x4_trans(bfr[nt], addr);
            }
#pragma unroll
            for (int mi = 0; mi < 2; mi++)
#pragma unroll
                for (int nj = 0; nj < 8; nj++)
                    mma16816(acc[mi][nj], afr[mi],
                             bfr[nj >> 1][(nj & 1) * 2], bfr[nj >> 1][(nj & 1) * 2 + 1]);
        }
    }

    // Epilogue
#pragma unroll
    for (int mi = 0; mi < 2; mi++) {
#pragma unroll
        for (int half = 0; half < 2; half++) {
            int o = o0 + wm * 32 + mi * 16 + half * 8 + (lane >> 2);
            float bv;
            float* dst;
            if (mode == 0) {
                int c2 = o / 3;
                int j  = o - c2 * 3;
                bv = bias[g * 768 + o];
                if (j == 0)      dst = g_Q + ((size_t)bg * DIM_ + c2) * S_;
                else if (j == 1) dst = g_K + ((size_t)bg * DIM_ + c2) * SPAD;
                else             dst = g_V + ((size_t)bg * DIM_ + c2) * SPAD;
            } else {
                bv  = bias[g * 256 + o];
                dst = out + ((size_t)bg * 256 + o) * S_;
            }
            dst += t0 + wn * 64 + (lane & 3) * 2;
#pragma unroll
            for (int nj = 0; nj < 8; nj++) {
                float2 v;
                v.x = acc[mi][nj][half * 2 + 0] + bv;
                v.y = acc[mi][nj][half * 2 + 1] + bv;
                *reinterpret_cast<float2*>(dst + nj * 8) = v;
            }
        }
    }
}

// ---------------------------------------------------------------------------
// Fill K/V pad column t=4096 with bias
// ---------------------------------------------------------------------------
__global__ void fill_pad(const float* __restrict__ b_qkv) {
    int i = blockIdx.x * 256 + threadIdx.x;  // 32*256
    int bg = i >> 8, c2 = i & 255, g = bg & 7;
    g_K[((size_t)bg * DIM_ + c2) * SPAD + S_] = b_qkv[g * 768 + c2 * 3 + 1];
    g_V[((size_t)bg * DIM_ + c2) * SPAD + S_] = b_qkv[g * 768 + c2 * 3 + 2];
}

// ---------------------------------------------------------------------------
// Attention: thread = (b, n, s, g-pair). Each thread owns 2 g's (sum over e
// only, so g never reduces across threads). 4 warp-rows reuse K/V via L1.
// Writes attn_out fp32 and attention-output hi/lo bf16 into g_Bo.
// ---------------------------------------------------------------------------
__global__ __launch_bounds__(256)
void attn_kernel(float* __restrict__ attn_out) {
    const int s  = blockIdx.x * 64 + threadIdx.x;   // 64 s-lanes
    const int gp = threadIdx.y;                     // 0..3 (g pair)
    const int n  = blockIdx.y;
    const int b  = blockIdx.z;
    const int g0 = gp * 2;

    float sc[2][16];
#pragma unroll
    for (int gi = 0; gi < 2; gi++)
#pragma unroll
        for (int e = 0; e < 16; e++) sc[gi][e] = 0.f;

    const size_t qbase = ((size_t)b * G_ * DIM_ + g0 * DIM_ + n * 32) * S_ + s;
    const size_t kbase = ((size_t)b * G_ * DIM_ + n * 32) * SPAD + s;

#pragma unroll 4
    for (int d = 0; d < 32; d++) {
        float qv[2], kv[16];
        qv[0] = g_Q[qbase + (size_t)d * S_];
        qv[1] = g_Q[qbase + (size_t)(DIM_ + d) * S_];
#pragma unroll
        for (int e = 0; e < 8; e++) {
            size_t ko = kbase + (size_t)(e * DIM_ + d) * SPAD;
            kv[e]     = g_K[ko];
            kv[e + 8] = g_K[ko + 1];
        }
#pragma unroll
        for (int gi = 0; gi < 2; gi++)
#pragma unroll
            for (int e = 0; e < 16; e++) sc[gi][e] += qv[gi] * kv[e];
    }

    const float scale = 0.17677669529663687f;  // 1/sqrt(32)
    const size_t abase = (size_t)(b * NH_ + n) * 128 * S_ + s;
#pragma unroll
    for (int gi = 0; gi < 2; gi++) {
        float rs = 1e-9f;
#pragma unroll
        for (int e = 0; e < 16; e++) {
            float z = 1.f / (1.f + __expf(-sc[gi][e] * scale));
            sc[gi][e] = z;
            rs += z;
        }
        float inv = 1.f / rs;
#pragma unroll
        for (int e = 0; e < 16; e++) {
            sc[gi][e] *= inv;
            attn_out[abase + (size_t)((g0 + gi) * 16 + e) * S_] = sc[gi][e];
        }
    }

    // AV + hi/lo write into g_Bo[bg][c]=hi, [bg][256+c]=lo, c = n*32+d
#pragma unroll 2
    for (int d = 0; d < 32; d++) {
        float vv[16];
#pragma unroll
        for (int e = 0; e < 8; e++) {
            size_t vo = kbase + (size_t)(e * DIM_ + d) * SPAD;
            vv[e]     = g_V[vo];
            vv[e + 8] = g_V[vo + 1];
        }
#pragma unroll
        for (int gi = 0; gi < 2; gi++) {
            float a = 0.f;
#pragma unroll
            for (int e = 0; e < 16; e++) a += sc[gi][e] * vv[e];
            __nv_bfloat16 h = __float2bfloat16(a);
            __nv_bfloat16 l = __float2bfloat16(a - __bfloat162float(h));
            size_t base = ((size_t)(b * 8 + g0 + gi) * 512 + n * 32 + d) * S_ + s;
            g_Bo[base]            = h;
            g_Bo[base + 256 * S_] = l;
        }
    }
}

// ---------------------------------------------------------------------------
extern "C" void kernel_launch(void* const* d_in, const int* in_sizes, int n_in,
                              void* d_out, int out_size) {
    const float* x      = (const float*)d_in[0];
    const float* w_qkv  = (const float*)d_in[1];
    const float* b_qkv  = (const float*)d_in[2];
    const float* w_pred = (const float*)d_in[3];
    const float* b_pred = (const float*)d_in[4];

    float* pred = (float*)d_out;
    float* attn = pred + (size_t)B_ * HID_ * S_;

    void *pAq, *pAp, *pBx, *pBo;
    cudaGetSymbolAddress(&pAq, g_Aq);
    cudaGetSymbolAddress(&pAp, g_Ap);
    cudaGetSymbolAddress(&pBx, g_Bx);
    cudaGetSymbolAddress(&pBo, g_Bo);

    cudaFuncSetAttribute(gemm_mma, cudaFuncAttributeMaxDynamicSharedMemorySize, 65536);

    convert_w<<<(G_ * 768 * 256 + 255) / 256, 256>>>(w_qkv, (__nv_bfloat16*)pAq, G_ * 768 * 256);
    convert_w<<<(G_ * 256 * 256 + 255) / 256, 256>>>(w_pred, (__nv_bfloat16*)pAp, G_ * 256 * 256);
    convert_x<<<32 * 256 * 1024 / 256, 256>>>(x, (__nv_bfloat16*)pBx);

    gemm_mma<<<dim3(32, 6, 32), 256, 65536>>>((const __nv_bfloat16*)pAq,
                                              (const __nv_bfloat16*)pBx,
                                              b_qkv, 768, 0, nullptr);
    fill_pad<<<32, 256>>>(b_qkv);

    attn_kernel<<<dim3(S_ / 64, NH_, B_), dim3(64, 4)>>>(attn);

    gemm_mma<<<dim3(32, 2, 32), 256, 65536>>>((const __nv_bfloat16*)pAp,
                                              (const __nv_bfloat16*)pBo,
                                              b_pred, 256, 1, pred);
}

// round 6
// speedup vs baseline: 1.0805x; 1.0805x over previous
#include <cuda_runtime.h>
#include <cuda_bf16.h>
#include <cstdint>

// ---------------------------------------------------------------------------
// Problem constants
constexpr int B_   = 4;
constexpr int G_   = 8;
constexpr int NH_  = 8;
constexpr int DIM_ = 256;    // HID / G
constexpr int S_   = 4096;
constexpr int SPAD = 4104;   // padded K/V time pitch (S_+1, rounded to 8)
constexpr int HID_ = 2048;
constexpr int KP   = 768;    // stacked K for A operand (3 x 256: hi|lo|hi)

// ---------------------------------------------------------------------------
// Scratch (device globals; allocation is forbidden)
__device__ float g_Q[(size_t)B_ * G_ * DIM_ * S_];    // (bg, c, s)
__device__ float g_K[(size_t)B_ * G_ * DIM_ * SPAD];  // (bg, c, t) t in [0,4096]
__device__ float g_V[(size_t)B_ * G_ * DIM_ * SPAD];

// B operands in [bg][512 rows][4096 t]:  rows 0-255 = hi(c), rows 256-511 = lo(c)
__device__ __nv_bfloat16 g_Bx[(size_t)32 * 512 * S_];
__device__ __nv_bfloat16 g_Bo[(size_t)32 * 512 * S_];
__device__ __nv_bfloat16 g_Aq[(size_t)G_ * 768 * KP]; // w_qkv stacked [g][o][hi|lo|hi]
__device__ __nv_bfloat16 g_Ap[(size_t)G_ * 256 * KP]; // w_pred stacked

// ---------------------------------------------------------------------------
__device__ __forceinline__ uint32_t smem_u32(const void* p) {
    uint32_t a;
    asm("{ .reg .u64 t; cvta.to.shared.u64 t, %1; cvt.u32.u64 %0, t; }" : "=r"(a) : "l"(p));
    return a;
}
__device__ __forceinline__ void cp_async16(uint32_t dst, const void* src) {
    asm volatile("cp.async.cg.shared.global [%0], [%1], 16;" :: "r"(dst), "l"(src));
}
__device__ __forceinline__ void ldmatrix_x4(uint32_t* r, uint32_t addr) {
    asm volatile("ldmatrix.sync.aligned.m8n8.x4.shared.b16 {%0,%1,%2,%3}, [%4];"
                 : "=r"(r[0]), "=r"(r[1]), "=r"(r[2]), "=r"(r[3]) : "r"(addr));
}
__device__ __forceinline__ void ldmatrix_x4_trans(uint32_t* r, uint32_t addr) {
    asm volatile("ldmatrix.sync.aligned.m8n8.x4.trans.shared.b16 {%0,%1,%2,%3}, [%4];"
                 : "=r"(r[0]), "=r"(r[1]), "=r"(r[2]), "=r"(r[3]) : "r"(addr));
}
__device__ __forceinline__ void mma16816(float* c, const uint32_t* a, uint32_t b0, uint32_t b1) {
    asm volatile(
        "mma.sync.aligned.m16n8k16.row.col.f32.bf16.bf16.f32 "
        "{%0,%1,%2,%3}, {%4,%5,%6,%7}, {%8,%9}, {%0,%1,%2,%3};"
        : "+f"(c[0]), "+f"(c[1]), "+f"(c[2]), "+f"(c[3])
        : "r"(a[0]), "r"(a[1]), "r"(a[2]), "r"(a[3]), "r"(b0), "r"(b1));
}

// ---------------------------------------------------------------------------
// Weights [R][256] fp32 -> [R][768] bf16 stacked [hi | lo | hi]
// ---------------------------------------------------------------------------
__global__ void convert_w(const float* __restrict__ w, __nv_bfloat16* __restrict__ A,
                          int total) {
    int i = blockIdx.x * 256 + threadIdx.x;
    if (i >= total) return;
    int r = i >> 8, c = i & 255;
    float v = w[i];
    __nv_bfloat16 h = __float2bfloat16(v);
    __nv_bfloat16 l = __float2bfloat16(v - __bfloat162float(h));
    __nv_bfloat16* row = A + (size_t)r * KP;
    row[c] = h;
    row[256 + c] = l;
    row[512 + c] = h;
}

// ---------------------------------------------------------------------------
// x [bg][256 c][4096 t] fp32 -> g_Bx [bg][512][4096] bf16 (row c = hi, 256+c = lo)
// ---------------------------------------------------------------------------
__global__ __launch_bounds__(256)
void convert_x(const float* __restrict__ x, __nv_bfloat16* __restrict__ dst) {
    int i = blockIdx.x * 256 + threadIdx.x;  // over 32*256*1024 float4 slots
    int t4 = (i & 1023) << 2;
    int c  = (i >> 10) & 255;
    int bg = i >> 18;
    float4 v = *reinterpret_cast<const float4*>(x + ((size_t)bg * 256 + c) * S_ + t4);
    __nv_bfloat162 h0, h1, l0, l1;
    h0.x = __float2bfloat16(v.x); h0.y = __float2bfloat16(v.y);
    h1.x = __float2bfloat16(v.z); h1.y = __float2bfloat16(v.w);
    l0.x = __float2bfloat16(v.x - __bfloat162float(h0.x));
    l0.y = __float2bfloat16(v.y - __bfloat162float(h0.y));
    l1.x = __float2bfloat16(v.z - __bfloat162float(h1.x));
    l1.y = __float2bfloat16(v.w - __bfloat162float(h1.y));
    __nv_bfloat162* dh = reinterpret_cast<__nv_bfloat162*>(
        dst + ((size_t)bg * 512 + c) * S_ + t4);
    dh[0] = h0; dh[1] = h1;
    __nv_bfloat162* dl = reinterpret_cast<__nv_bfloat162*>(
        dst + ((size_t)bg * 512 + 256 + c) * S_ + t4);
    dl[0] = l0; dl[1] = l1;
}

// ---------------------------------------------------------------------------
// mma.sync GEMM: D[128 o x 128 t] = A[o][k'768] . B[t][k 512]
// 4 warps, warp tile 64x64 (2m x 2n), BK=32, 4-stage cp.async, 1 barrier/chunk.
// ch 0-7: Ah.Bh ; 8-15: Al.Bh ; 16-23: Ah.Bl
// ---------------------------------------------------------------------------
constexpr int NCH = 24;

__global__ __launch_bounds__(128, 2)
void gemm_mma(const __nv_bfloat16* __restrict__ Aall,
              const __nv_bfloat16* __restrict__ Ball,
              const float* __restrict__ bias,
              int Mtot, int mode, float* __restrict__ out) {
    // per stage: A 128(o)x32(k) 8KB (64B rows) + B 32(k)x128(t) 8KB (256B rows)
    extern __shared__ __align__(1024) char sbuf[];  // 4 * 16384
    const int tid  = threadIdx.x;
    const int lane = tid & 31;
    const int wid  = tid >> 5;
    const int wm   = wid & 1;   // m slice of 64
    const int wn   = wid >> 1;  // n slice of 64
    const int bg = blockIdx.z, g = bg & 7;
    const int o0 = blockIdx.y * 128, t0 = blockIdx.x * 128;

    const uint32_t sbase = smem_u32(sbuf);
    const __nv_bfloat16* A  = Aall + ((size_t)g * Mtot + o0) * KP;
    const __nv_bfloat16* Bp = Ball + (size_t)bg * 512 * S_;

    auto load_stage = [&](int ch, int st) {
        uint32_t sA = sbase + st * 16384;
        uint32_t sB = sA + 8192;
        const char* a8 = (const char*)A + (size_t)ch * 64;
        int bch = (ch < 8) ? ch : ch - 8;
        const char* b8 = (const char*)(Bp + ((size_t)bch * 32) * S_ + t0);
#pragma unroll
        for (int i = 0; i < 4; i++) {
            int id = tid + i * 128;
            int ra = id >> 2, ca = id & 3;
            uint32_t offA = ra * 64 + ((ca ^ ((ra >> 1) & 3)) << 4);
            cp_async16(sA + offA, a8 + (size_t)ra * (KP * 2) + ca * 16);
            int rb = id >> 4, cb = id & 15;
            uint32_t offB = rb * 256 + ((cb ^ (rb & 7)) << 4);
            cp_async16(sB + offB, b8 + (size_t)rb * (S_ * 2) + cb * 16);
        }
    };

    float acc[4][8][4];
#pragma unroll
    for (int mi = 0; mi < 4; mi++)
#pragma unroll
        for (int nj = 0; nj < 8; nj++)
#pragma unroll
            for (int q = 0; q < 4; q++) acc[mi][nj][q] = 0.f;

    load_stage(0, 0);
    asm volatile("cp.async.commit_group;" ::: "memory");
    load_stage(1, 1);
    asm volatile("cp.async.commit_group;" ::: "memory");
    load_stage(2, 2);
    asm volatile("cp.async.commit_group;" ::: "memory");

    const int gsel = lane >> 3;
    const int rin  = lane & 7;
    const int bl   = lane & 15;
    const int bh   = lane >> 4;

    for (int ch = 0; ch < NCH; ch++) {
        if (ch < NCH - 3) asm volatile("cp.async.wait_group 2;" ::: "memory");
        else              asm volatile("cp.async.wait_group 0;" ::: "memory");
        __syncthreads();
        if (ch + 3 < NCH) {
            load_stage(ch + 3, (ch + 3) & 3);
            asm volatile("cp.async.commit_group;" ::: "memory");
        }
        uint32_t sA = sbase + (ch & 3) * 16384;
        uint32_t sB = sA + 8192;
#pragma unroll
        for (int kk = 0; kk < 2; kk++) {
            uint32_t afr[4][4];
#pragma unroll
            for (int mi = 0; mi < 4; mi++) {
                int row   = wm * 64 + mi * 16 + (gsel & 1) * 8 + rin;
                int chunk = kk * 2 + (gsel >> 1);
                uint32_t addr = sA + row * 64 + ((chunk ^ ((row >> 1) & 3)) << 4);
                ldmatrix_x4(afr[mi], addr);
            }
            uint32_t bfr[4][4];
#pragma unroll
            for (int nt = 0; nt < 4; nt++) {
                int krow  = kk * 16 + bl;
                int chunk = wn * 8 + nt * 2 + bh;
                uint32_t addr = sB + krow * 256 + ((chunk ^ (krow & 7)) << 4);
                ldmatrix_x4_trans(bfr[nt], addr);
            }
#pragma unroll
            for (int mi = 0; mi < 4; mi++)
#pragma unroll
                for (int nj = 0; nj < 8; nj++)
                    mma16816(acc[mi][nj], afr[mi],
                             bfr[nj >> 1][(nj & 1) * 2], bfr[nj >> 1][(nj & 1) * 2 + 1]);
        }
    }

    // Epilogue
#pragma unroll
    for (int mi = 0; mi < 4; mi++) {
#pragma unroll
        for (int half = 0; half < 2; half++) {
            int o = o0 + wm * 64 + mi * 16 + half * 8 + (lane >> 2);
            float bv;
            float* dst;
            if (mode == 0) {
                int c2 = o / 3;
                int j  = o - c2 * 3;
                bv = bias[g * 768 + o];
                if (j == 0)      dst = g_Q + ((size_t)bg * DIM_ + c2) * S_;
                else if (j == 1) dst = g_K + ((size_t)bg * DIM_ + c2) * SPAD;
                else             dst = g_V + ((size_t)bg * DIM_ + c2) * SPAD;
            } else {
                bv  = bias[g * 256 + o];
                dst = out + ((size_t)bg * 256 + o) * S_;
            }
            dst += t0 + wn * 64 + (lane & 3) * 2;
#pragma unroll
            for (int nj = 0; nj < 8; nj++) {
                float2 v;
                v.x = acc[mi][nj][half * 2 + 0] + bv;
                v.y = acc[mi][nj][half * 2 + 1] + bv;
                *reinterpret_cast<float2*>(dst + nj * 8) = v;
            }
        }
    }
}

// ---------------------------------------------------------------------------
// Fill K/V pad column t=4096 with bias
// ---------------------------------------------------------------------------
__global__ void fill_pad(const float* __restrict__ b_qkv) {
    int i = blockIdx.x * 256 + threadIdx.x;  // 32*256
    int bg = i >> 8, c2 = i & 255, g = bg & 7;
    g_K[((size_t)bg * DIM_ + c2) * SPAD + S_] = b_qkv[g * 768 + c2 * 3 + 1];
    g_V[((size_t)bg * DIM_ + c2) * SPAD + S_] = b_qkv[g * 768 + c2 * 3 + 2];
}

// ---------------------------------------------------------------------------
// Attention: one thread per (b, n, s). Writes attn_out fp32 and the attention
// output DIRECTLY as hi/lo bf16 into g_Bo (pred GEMM's B operand).
// ---------------------------------------------------------------------------
__global__ __launch_bounds__(128)
void attn_kernel(float* __restrict__ attn_out) {
    const int s = blockIdx.x * 128 + threadIdx.x;
    const int n = blockIdx.y;
    const int b = blockIdx.z;

    float sc[8][16];
#pragma unroll
    for (int g = 0; g < 8; g++)
#pragma unroll
        for (int e = 0; e < 16; e++) sc[g][e] = 0.f;

    const size_t qbase = ((size_t)b * G_ * DIM_ + n * 32) * S_ + s;
    const size_t kbase = ((size_t)b * G_ * DIM_ + n * 32) * SPAD + s;

#pragma unroll 4
    for (int d = 0; d < 32; d++) {
        float qv[8], kv[16];
#pragma unroll
        for (int g = 0; g < 8; g++)
            qv[g] = g_Q[qbase + (size_t)(g * DIM_ + d) * S_];
#pragma unroll
        for (int e = 0; e < 8; e++) {
            size_t ko = kbase + (size_t)(e * DIM_ + d) * SPAD;
            kv[e]     = g_K[ko];
            kv[e + 8] = g_K[ko + 1];
        }
#pragma unroll
        for (int g = 0; g < 8; g++)
#pragma unroll
            for (int e = 0; e < 16; e++) sc[g][e] += qv[g] * kv[e];
    }

    const float scale = 0.17677669529663687f;  // 1/sqrt(32)
    const size_t abase = (size_t)(b * NH_ + n) * 128 * S_ + s;
#pragma unroll
    for (int g = 0; g < 8; g++) {
        float rs = 1e-9f;
#pragma unroll
        for (int e = 0; e < 16; e++) {
            float z = 1.f / (1.f + __expf(-sc[g][e] * scale));
            sc[g][e] = z;
            rs += z;
        }
        float inv = 1.f / rs;
#pragma unroll
        for (int e = 0; e < 16; e++) {
            sc[g][e] *= inv;
            attn_out[abase + (size_t)(g * 16 + e) * S_] = sc[g][e];
        }
    }

    // AV + direct hi/lo write into g_Bo[bg][c]=hi, [bg][256+c]=lo, c = n*32+d
#pragma unroll 2
    for (int d = 0; d < 32; d++) {
        float vv[16];
#pragma unroll
        for (int e = 0; e < 8; e++) {
            size_t vo = kbase + (size_t)(e * DIM_ + d) * SPAD;
            vv[e]     = g_V[vo];
            vv[e + 8] = g_V[vo + 1];
        }
#pragma unroll
        for (int g = 0; g < 8; g++) {
            float a = 0.f;
#pragma unroll
            for (int e = 0; e < 16; e++) a += sc[g][e] * vv[e];
            __nv_bfloat16 h = __float2bfloat16(a);
            __nv_bfloat16 l = __float2bfloat16(a - __bfloat162float(h));
            size_t base = ((size_t)(b * 8 + g) * 512 + n * 32 + d) * S_ + s;
            g_Bo[base]            = h;
            g_Bo[base + 256 * S_] = l;
        }
    }
}

// ---------------------------------------------------------------------------
extern "C" void kernel_launch(void* const* d_in, const int* in_sizes, int n_in,
                              void* d_out, int out_size) {
    const float* x      = (const float*)d_in[0];
    const float* w_qkv  = (const float*)d_in[1];
    const float* b_qkv  = (const float*)d_in[2];
    const float* w_pred = (const float*)d_in[3];
    const float* b_pred = (const float*)d_in[4];

    float* pred = (float*)d_out;
    float* attn = pred + (size_t)B_ * HID_ * S_;

    void *pAq, *pAp, *pBx, *pBo;
    cudaGetSymbolAddress(&pAq, g_Aq);
    cudaGetSymbolAddress(&pAp, g_Ap);
    cudaGetSymbolAddress(&pBx, g_Bx);
    cudaGetSymbolAddress(&pBo, g_Bo);

    cudaFuncSetAttribute(gemm_mma, cudaFuncAttributeMaxDynamicSharedMemorySize, 65536);

    convert_w<<<(G_ * 768 * 256 + 255) / 256, 256>>>(w_qkv, (__nv_bfloat16*)pAq, G_ * 768 * 256);
    convert_w<<<(G_ * 256 * 256 + 255) / 256, 256>>>(w_pred, (__nv_bfloat16*)pAp, G_ * 256 * 256);
    convert_x<<<32 * 256 * 1024 / 256, 256>>>(x, (__nv_bfloat16*)pBx);

    gemm_mma<<<dim3(32, 6, 32), 128, 65536>>>((const __nv_bfloat16*)pAq,
                                              (const __nv_bfloat16*)pBx,
                                              b_qkv, 768, 0, nullptr);
    fill_pad<<<32, 256>>>(b_qkv);

    attn_kernel<<<dim3(S_ / 128, NH_, B_), 128>>>(attn);

    gemm_mma<<<dim3(32, 2, 32), 128, 65536>>>((const __nv_bfloat16*)pAp,
                                              (const __nv_bfloat16*)pBo,
                                              b_pred, 256, 1, pred);
}

// round 7
// speedup vs baseline: 1.3472x; 1.2468x over previous
#include <cuda_runtime.h>
#include <cuda_fp16.h>
#include <cstdint>

// ---------------------------------------------------------------------------
// Problem constants
constexpr int B_   = 4;
constexpr int G_   = 8;
constexpr int NH_  = 8;
constexpr int DIM_ = 256;    // HID / G
constexpr int S_   = 4096;
constexpr int SPAD = 4104;   // padded K/V time pitch (S_+1, rounded to 8)
constexpr int HID_ = 2048;
constexpr int KP   = 512;    // stacked K for A operand (2 x 256: hi|lo)

// ---------------------------------------------------------------------------
// Scratch (device globals; allocation is forbidden)
__device__ float g_Q[(size_t)B_ * G_ * DIM_ * S_];    // (bg, c, s)
__device__ float g_K[(size_t)B_ * G_ * DIM_ * SPAD];  // (bg, c, t) t in [0,4096]
__device__ float g_V[(size_t)B_ * G_ * DIM_ * SPAD];

// B operands: [bg][256 rows][4096 t] single fp16
__device__ __half g_Bx[(size_t)32 * 256 * S_];
__device__ __half g_Bo[(size_t)32 * 256 * S_];
__device__ __half g_Aq[(size_t)G_ * 768 * KP];  // w_qkv stacked [g][o][hi|lo]
__device__ __half g_Ap[(size_t)G_ * 256 * KP];  // w_pred stacked

// ---------------------------------------------------------------------------
__device__ __forceinline__ uint32_t smem_u32(const void* p) {
    uint32_t a;
    asm("{ .reg .u64 t; cvta.to.shared.u64 t, %1; cvt.u32.u64 %0, t; }" : "=r"(a) : "l"(p));
    return a;
}
__device__ __forceinline__ void cp_async16(uint32_t dst, const void* src) {
    asm volatile("cp.async.cg.shared.global [%0], [%1], 16;" :: "r"(dst), "l"(src));
}
__device__ __forceinline__ void ldmatrix_x4(uint32_t* r, uint32_t addr) {
    asm volatile("ldmatrix.sync.aligned.m8n8.x4.shared.b16 {%0,%1,%2,%3}, [%4];"
                 : "=r"(r[0]), "=r"(r[1]), "=r"(r[2]), "=r"(r[3]) : "r"(addr));
}
__device__ __forceinline__ void ldmatrix_x4_trans(uint32_t* r, uint32_t addr) {
    asm volatile("ldmatrix.sync.aligned.m8n8.x4.trans.shared.b16 {%0,%1,%2,%3}, [%4];"
                 : "=r"(r[0]), "=r"(r[1]), "=r"(r[2]), "=r"(r[3]) : "r"(addr));
}
__device__ __forceinline__ void mma16816(float* c, const uint32_t* a, uint32_t b0, uint32_t b1) {
    asm volatile(
        "mma.sync.aligned.m16n8k16.row.col.f32.f16.f16.f32 "
        "{%0,%1,%2,%3}, {%4,%5,%6,%7}, {%8,%9}, {%0,%1,%2,%3};"
        : "+f"(c[0]), "+f"(c[1]), "+f"(c[2]), "+f"(c[3])
        : "r"(a[0]), "r"(a[1]), "r"(a[2]), "r"(a[3]), "r"(b0), "r"(b1));
}

// ---------------------------------------------------------------------------
// Weights [R][256] fp32 -> [R][512] fp16 stacked [hi | lo]
// ---------------------------------------------------------------------------
__global__ void convert_w(const float* __restrict__ w, __half* __restrict__ A,
                          int total) {
    int i = blockIdx.x * 256 + threadIdx.x;
    if (i >= total) return;
    int r = i >> 8, c = i & 255;
    float v = w[i];
    __half h = __float2half(v);
    __half l = __float2half(v - __half2float(h));
    __half* row = A + (size_t)r * KP;
    row[c] = h;
    row[256 + c] = l;
}

// ---------------------------------------------------------------------------
// x [bg][256 c][4096 t] fp32 -> g_Bx [bg][256][4096] fp16
// ---------------------------------------------------------------------------
__global__ __launch_bounds__(256)
void convert_x(const float* __restrict__ x, __half* __restrict__ dst) {
    int i = blockIdx.x * 256 + threadIdx.x;  // over 32*256*1024 float4 slots
    int t4 = (i & 1023) << 2;
    int c  = (i >> 10) & 255;
    int bg = i >> 18;
    float4 v = *reinterpret_cast<const float4*>(x + ((size_t)bg * 256 + c) * S_ + t4);
    __half2 h0, h1;
    h0.x = __float2half(v.x); h0.y = __float2half(v.y);
    h1.x = __float2half(v.z); h1.y = __float2half(v.w);
    __half2* dh = reinterpret_cast<__half2*>(dst + ((size_t)bg * 256 + c) * S_ + t4);
    dh[0] = h0; dh[1] = h1;
}

// ---------------------------------------------------------------------------
// mma.sync GEMM: D[128 o x 128 t] = A[o][k'512] . B[t][k 256]
// 4 warps, warp tile 64x64 (2m x 2n), BK=32, 4-stage cp.async, 1 barrier/chunk.
// ch 0-7: Ah.B ; ch 8-15: Al.B  (bch = ch & 7)
// ---------------------------------------------------------------------------
constexpr int NCH = 16;

__global__ __launch_bounds__(128, 2)
void gemm_mma(const __half* __restrict__ Aall,
              const __half* __restrict__ Ball,
              const float* __restrict__ bias,
              int Mtot, int mode, float* __restrict__ out) {
    // per stage: A 128(o)x32(k) 8KB (64B rows) + B 32(k)x128(t) 8KB (256B rows)
    extern __shared__ __align__(1024) char sbuf[];  // 4 * 16384
    const int tid  = threadIdx.x;
    const int lane = tid & 31;
    const int wid  = tid >> 5;
    const int wm   = wid & 1;   // m slice of 64
    const int wn   = wid >> 1;  // n slice of 64
    const int bg = blockIdx.z, g = bg & 7;
    const int o0 = blockIdx.y * 128, t0 = blockIdx.x * 128;

    const uint32_t sbase = smem_u32(sbuf);
    const __half* A  = Aall + ((size_t)g * Mtot + o0) * KP;
    const __half* Bp = Ball + (size_t)bg * 256 * S_;

    auto load_stage = [&](int ch, int st) {
        uint32_t sA = sbase + st * 16384;
        uint32_t sB = sA + 8192;
        const char* a8 = (const char*)A + (size_t)ch * 64;
        int bch = ch & 7;
        const char* b8 = (const char*)(Bp + ((size_t)bch * 32) * S_ + t0);
#pragma unroll
        for (int i = 0; i < 4; i++) {
            int id = tid + i * 128;
            int ra = id >> 2, ca = id & 3;
            uint32_t offA = ra * 64 + ((ca ^ ((ra >> 1) & 3)) << 4);
            cp_async16(sA + offA, a8 + (size_t)ra * (KP * 2) + ca * 16);
            int rb = id >> 4, cb = id & 15;
            uint32_t offB = rb * 256 + ((cb ^ (rb & 7)) << 4);
            cp_async16(sB + offB, b8 + (size_t)rb * (S_ * 2) + cb * 16);
        }
    };

    float acc[4][8][4];
#pragma unroll
    for (int mi = 0; mi < 4; mi++)
#pragma unroll
        for (int nj = 0; nj < 8; nj++)
#pragma unroll
            for (int q = 0; q < 4; q++) acc[mi][nj][q] = 0.f;

    load_stage(0, 0);
    asm volatile("cp.async.commit_group;" ::: "memory");
    load_stage(1, 1);
    asm volatile("cp.async.commit_group;" ::: "memory");
    load_stage(2, 2);
    asm volatile("cp.async.commit_group;" ::: "memory");

    const int gsel = lane >> 3;
    const int rin  = lane & 7;
    const int bl   = lane & 15;
    const int bh   = lane >> 4;

    for (int ch = 0; ch < NCH; ch++) {
        if (ch < NCH - 3) asm volatile("cp.async.wait_group 2;" ::: "memory");
        else              asm volatile("cp.async.wait_group 0;" ::: "memory");
        __syncthreads();
        if (ch + 3 < NCH) {
            load_stage(ch + 3, (ch + 3) & 3);
            asm volatile("cp.async.commit_group;" ::: "memory");
        }
        uint32_t sA = sbase + (ch & 3) * 16384;
        uint32_t sB = sA + 8192;
#pragma unroll
        for (int kk = 0; kk < 2; kk++) {
            uint32_t afr[4][4];
#pragma unroll
            for (int mi = 0; mi < 4; mi++) {
                int row   = wm * 64 + mi * 16 + (gsel & 1) * 8 + rin;
                int chunk = kk * 2 + (gsel >> 1);
                uint32_t addr = sA + row * 64 + ((chunk ^ ((row >> 1) & 3)) << 4);
                ldmatrix_x4(afr[mi], addr);
            }
            uint32_t bfr[4][4];
#pragma unroll
            for (int nt = 0; nt < 4; nt++) {
                int krow  = kk * 16 + bl;
                int chunk = wn * 8 + nt * 2 + bh;
                uint32_t addr = sB + krow * 256 + ((chunk ^ (krow & 7)) << 4);
                ldmatrix_x4_trans(bfr[nt], addr);
            }
#pragma unroll
            for (int mi = 0; mi < 4; mi++)
#pragma unroll
                for (int nj = 0; nj < 8; nj++)
                    mma16816(acc[mi][nj], afr[mi],
                             bfr[nj >> 1][(nj & 1) * 2], bfr[nj >> 1][(nj & 1) * 2 + 1]);
        }
    }

    // Epilogue
#pragma unroll
    for (int mi = 0; mi < 4; mi++) {
#pragma unroll
        for (int half = 0; half < 2; half++) {
            int o = o0 + wm * 64 + mi * 16 + half * 8 + (lane >> 2);
            float bv;
            float* dst;
            if (mode == 0) {
                int c2 = o / 3;
                int j  = o - c2 * 3;
                bv = bias[g * 768 + o];
                if (j == 0)      dst = g_Q + ((size_t)bg * DIM_ + c2) * S_;
                else if (j == 1) dst = g_K + ((size_t)bg * DIM_ + c2) * SPAD;
                else             dst = g_V + ((size_t)bg * DIM_ + c2) * SPAD;
            } else {
                bv  = bias[g * 256 + o];
                dst = out + ((size_t)bg * 256 + o) * S_;
            }
            dst += t0 + wn * 64 + (lane & 3) * 2;
#pragma unroll
            for (int nj = 0; nj < 8; nj++) {
                float2 v;
                v.x = acc[mi][nj][half * 2 + 0] + bv;
                v.y = acc[mi][nj][half * 2 + 1] + bv;
                *reinterpret_cast<float2*>(dst + nj * 8) = v;
            }
        }
    }
}

// ---------------------------------------------------------------------------
// Fill K/V pad column t=4096 with bias
// ---------------------------------------------------------------------------
__global__ void fill_pad(const float* __restrict__ b_qkv) {
    int i = blockIdx.x * 256 + threadIdx.x;  // 32*256
    int bg = i >> 8, c2 = i & 255, g = bg & 7;
    g_K[((size_t)bg * DIM_ + c2) * SPAD + S_] = b_qkv[g * 768 + c2 * 3 + 1];
    g_V[((size_t)bg * DIM_ + c2) * SPAD + S_] = b_qkv[g * 768 + c2 * 3 + 2];
}

// ---------------------------------------------------------------------------
// Attention: one thread per (b, n, s). Writes attn_out fp32 and the attention
// output DIRECTLY as fp16 into g_Bo (pred GEMM's B operand).
// ---------------------------------------------------------------------------
__global__ __launch_bounds__(128)
void attn_kernel(float* __restrict__ attn_out) {
    const int s = blockIdx.x * 128 + threadIdx.x;
    const int n = blockIdx.y;
    const int b = blockIdx.z;

    float sc[8][16];
#pragma unroll
    for (int g = 0; g < 8; g++)
#pragma unroll
        for (int e = 0; e < 16; e++) sc[g][e] = 0.f;

    const size_t qbase = ((size_t)b * G_ * DIM_ + n * 32) * S_ + s;
    const size_t kbase = ((size_t)b * G_ * DIM_ + n * 32) * SPAD + s;

#pragma unroll 4
    for (int d = 0; d < 32; d++) {
        float qv[8], kv[16];
#pragma unroll
        for (int g = 0; g < 8; g++)
            qv[g] = g_Q[qbase + (size_t)(g * DIM_ + d) * S_];
#pragma unroll
        for (int e = 0; e < 8; e++) {
            size_t ko = kbase + (size_t)(e * DIM_ + d) * SPAD;
            kv[e]     = g_K[ko];
            kv[e + 8] = g_K[ko + 1];
        }
#pragma unroll
        for (int g = 0; g < 8; g++)
#pragma unroll
            for (int e = 0; e < 16; e++) sc[g][e] += qv[g] * kv[e];
    }

    const float scale = 0.17677669529663687f;  // 1/sqrt(32)
    const size_t abase = (size_t)(b * NH_ + n) * 128 * S_ + s;
#pragma unroll
    for (int g = 0; g < 8; g++) {
        float rs = 1e-9f;
#pragma unroll
        for (int e = 0; e < 16; e++) {
            float z = 1.f / (1.f + __expf(-sc[g][e] * scale));
            sc[g][e] = z;
            rs += z;
        }
        float inv = 1.f / rs;
#pragma unroll
        for (int e = 0; e < 16; e++) {
            sc[g][e] *= inv;
            attn_out[abase + (size_t)(g * 16 + e) * S_] = sc[g][e];
        }
    }

    // AV + direct fp16 write into g_Bo[bg][c], c = n*32+d
#pragma unroll 2
    for (int d = 0; d < 32; d++) {
        float vv[16];
#pragma unroll
        for (int e = 0; e < 8; e++) {
            size_t vo = kbase + (size_t)(e * DIM_ + d) * SPAD;
            vv[e]     = g_V[vo];
            vv[e + 8] = g_V[vo + 1];
        }
#pragma unroll
        for (int g = 0; g < 8; g++) {
            float a = 0.f;
#pragma unroll
            for (int e = 0; e < 16; e++) a += sc[g][e] * vv[e];
            g_Bo[((size_t)(b * 8 + g) * 256 + n * 32 + d) * S_ + s] = __float2half(a);
        }
    }
}

// ---------------------------------------------------------------------------
extern "C" void kernel_launch(void* const* d_in, const int* in_sizes, int n_in,
                              void* d_out, int out_size) {
    const float* x      = (const float*)d_in[0];
    const float* w_qkv  = (const float*)d_in[1];
    const float* b_qkv  = (const float*)d_in[2];
    const float* w_pred = (const float*)d_in[3];
    const float* b_pred = (const float*)d_in[4];

    float* pred = (float*)d_out;
    float* attn = pred + (size_t)B_ * HID_ * S_;

    void *pAq, *pAp, *pBx, *pBo;
    cudaGetSymbolAddress(&pAq, g_Aq);
    cudaGetSymbolAddress(&pAp, g_Ap);
    cudaGetSymbolAddress(&pBx, g_Bx);
    cudaGetSymbolAddress(&pBo, g_Bo);

    cudaFuncSetAttribute(gemm_mma, cudaFuncAttributeMaxDynamicSharedMemorySize, 65536);

    convert_w<<<(G_ * 768 * 256 + 255) / 256, 256>>>(w_qkv, (__half*)pAq, G_ * 768 * 256);
    convert_w<<<(G_ * 256 * 256 + 255) / 256, 256>>>(w_pred, (__half*)pAp, G_ * 256 * 256);
    convert_x<<<32 * 256 * 1024 / 256, 256>>>(x, (__half*)pBx);

    gemm_mma<<<dim3(32, 6, 32), 128, 65536>>>((const __half*)pAq,
                                              (const __half*)pBx,
                                              b_qkv, 768, 0, nullptr);
    fill_pad<<<32, 256>>>(b_qkv);

    attn_kernel<<<dim3(S_ / 128, NH_, B_), 128>>>(attn);

    gemm_mma<<<dim3(32, 2, 32), 128, 65536>>>((const __half*)pAp,
                                              (const __half*)pBo,
                                              b_pred, 256, 1, pred);
}

// round 8
// speedup vs baseline: 1.6673x; 1.2376x over previous
#include <cuda_runtime.h>
#include <cuda_fp16.h>
#include <cstdint>

// ---------------------------------------------------------------------------
// Problem constants
constexpr int B_   = 4;
constexpr int G_   = 8;
constexpr int NH_  = 8;
constexpr int DIM_ = 256;    // HID / G
constexpr int S_   = 4096;
constexpr int SPAD = 4104;   // padded K/V time pitch (S_+1, rounded to 8)
constexpr int HID_ = 2048;
constexpr int KP   = 256;    // K (plain fp16, single term)

// ---------------------------------------------------------------------------
// Scratch (device globals; allocation is forbidden)
__device__ float g_Q[(size_t)B_ * G_ * DIM_ * S_];    // (bg, c, s)
__device__ float g_K[(size_t)B_ * G_ * DIM_ * SPAD];  // (bg, c, t) t in [0,4096]
__device__ float g_V[(size_t)B_ * G_ * DIM_ * SPAD];

// B operands: [bg][256 rows][4096 t] fp16
__device__ __half g_Bx[(size_t)32 * 256 * S_];
__device__ __half g_Bo[(size_t)32 * 256 * S_];
__device__ __half g_Aq[(size_t)G_ * 768 * KP];  // w_qkv fp16 [g][o][c]
__device__ __half g_Ap[(size_t)G_ * 256 * KP];  // w_pred fp16

// ---------------------------------------------------------------------------
__device__ __forceinline__ uint32_t smem_u32(const void* p) {
    uint32_t a;
    asm("{ .reg .u64 t; cvta.to.shared.u64 t, %1; cvt.u32.u64 %0, t; }" : "=r"(a) : "l"(p));
    return a;
}
__device__ __forceinline__ void cp_async16(uint32_t dst, const void* src) {
    asm volatile("cp.async.cg.shared.global [%0], [%1], 16;" :: "r"(dst), "l"(src));
}
__device__ __forceinline__ void ldmatrix_x4(uint32_t* r, uint32_t addr) {
    asm volatile("ldmatrix.sync.aligned.m8n8.x4.shared.b16 {%0,%1,%2,%3}, [%4];"
                 : "=r"(r[0]), "=r"(r[1]), "=r"(r[2]), "=r"(r[3]) : "r"(addr));
}
__device__ __forceinline__ void ldmatrix_x4_trans(uint32_t* r, uint32_t addr) {
    asm volatile("ldmatrix.sync.aligned.m8n8.x4.trans.shared.b16 {%0,%1,%2,%3}, [%4];"
                 : "=r"(r[0]), "=r"(r[1]), "=r"(r[2]), "=r"(r[3]) : "r"(addr));
}
__device__ __forceinline__ void mma16816(float* c, const uint32_t* a, uint32_t b0, uint32_t b1) {
    asm volatile(
        "mma.sync.aligned.m16n8k16.row.col.f32.f16.f16.f32 "
        "{%0,%1,%2,%3}, {%4,%5,%6,%7}, {%8,%9}, {%0,%1,%2,%3};"
        : "+f"(c[0]), "+f"(c[1]), "+f"(c[2]), "+f"(c[3])
        : "r"(a[0]), "r"(a[1]), "r"(a[2]), "r"(a[3]), "r"(b0), "r"(b1));
}

// ---------------------------------------------------------------------------
// Weights [R][256] fp32 -> fp16
// ---------------------------------------------------------------------------
__global__ void convert_w(const float* __restrict__ w, __half* __restrict__ A,
                          int total) {
    int i = blockIdx.x * 256 + threadIdx.x;
    if (i >= total) return;
    A[i] = __float2half(w[i]);
}

// ---------------------------------------------------------------------------
// x [bg][256 c][4096 t] fp32 -> g_Bx fp16
// ---------------------------------------------------------------------------
__global__ __launch_bounds__(256)
void convert_x(const float* __restrict__ x, __half* __restrict__ dst) {
    int i = blockIdx.x * 256 + threadIdx.x;  // over 32*256*1024 float4 slots
    size_t base = (size_t)i << 2;
    float4 v = *reinterpret_cast<const float4*>(x + base);
    __half2 h0, h1;
    h0.x = __float2half(v.x); h0.y = __float2half(v.y);
    h1.x = __float2half(v.z); h1.y = __float2half(v.w);
    __half2* dh = reinterpret_cast<__half2*>(dst + base);
    dh[0] = h0; dh[1] = h1;
}

// ---------------------------------------------------------------------------
// mma.sync GEMM: D[128 o x 128 t] = A[o][k 256] . B[t][k 256]
// 4 warps, warp tile 64x64 (2m x 2n), BK=32, 4-stage cp.async, 1 barrier/chunk.
// ---------------------------------------------------------------------------
constexpr int NCH = 8;

__global__ __launch_bounds__(128, 2)
void gemm_mma(const __half* __restrict__ Aall,
              const __half* __restrict__ Ball,
              const float* __restrict__ bias,
              int Mtot, int mode, float* __restrict__ out) {
    // per stage: A 128(o)x32(k) 8KB (64B rows) + B 32(k)x128(t) 8KB (256B rows)
    extern __shared__ __align__(1024) char sbuf[];  // 4 * 16384
    const int tid  = threadIdx.x;
    const int lane = tid & 31;
    const int wid  = tid >> 5;
    const int wm   = wid & 1;   // m slice of 64
    const int wn   = wid >> 1;  // n slice of 64
    const int bg = blockIdx.z, g = bg & 7;
    const int o0 = blockIdx.y * 128, t0 = blockIdx.x * 128;

    const uint32_t sbase = smem_u32(sbuf);
    const __half* A  = Aall + ((size_t)g * Mtot + o0) * KP;
    const __half* Bp = Ball + (size_t)bg * 256 * S_;

    auto load_stage = [&](int ch, int st) {
        uint32_t sA = sbase + st * 16384;
        uint32_t sB = sA + 8192;
        const char* a8 = (const char*)A + (size_t)ch * 64;
        const char* b8 = (const char*)(Bp + ((size_t)ch * 32) * S_ + t0);
#pragma unroll
        for (int i = 0; i < 4; i++) {
            int id = tid + i * 128;
            int ra = id >> 2, ca = id & 3;
            uint32_t offA = ra * 64 + ((ca ^ ((ra >> 1) & 3)) << 4);
            cp_async16(sA + offA, a8 + (size_t)ra * (KP * 2) + ca * 16);
            int rb = id >> 4, cb = id & 15;
            uint32_t offB = rb * 256 + ((cb ^ (rb & 7)) << 4);
            cp_async16(sB + offB, b8 + (size_t)rb * (S_ * 2) + cb * 16);
        }
    };

    float acc[4][8][4];
#pragma unroll
    for (int mi = 0; mi < 4; mi++)
#pragma unroll
        for (int nj = 0; nj < 8; nj++)
#pragma unroll
            for (int q = 0; q < 4; q++) acc[mi][nj][q] = 0.f;

    load_stage(0, 0);
    asm volatile("cp.async.commit_group;" ::: "memory");
    load_stage(1, 1);
    asm volatile("cp.async.commit_group;" ::: "memory");
    load_stage(2, 2);
    asm volatile("cp.async.commit_group;" ::: "memory");

    const int gsel = lane >> 3;
    const int rin  = lane & 7;
    const int bl   = lane & 15;
    const int bh   = lane >> 4;

    for (int ch = 0; ch < NCH; ch++) {
        if (ch < NCH - 3) asm volatile("cp.async.wait_group 2;" ::: "memory");
        else              asm volatile("cp.async.wait_group 0;" ::: "memory");
        __syncthreads();
        if (ch + 3 < NCH) {
            load_stage(ch + 3, (ch + 3) & 3);
            asm volatile("cp.async.commit_group;" ::: "memory");
        }
        uint32_t sA = sbase + (ch & 3) * 16384;
        uint32_t sB = sA + 8192;
#pragma unroll
        for (int kk = 0; kk < 2; kk++) {
            uint32_t afr[4][4];
#pragma unroll
            for (int mi = 0; mi < 4; mi++) {
                int row   = wm * 64 + mi * 16 + (gsel & 1) * 8 + rin;
                int chunk = kk * 2 + (gsel >> 1);
                uint32_t addr = sA + row * 64 + ((chunk ^ ((row >> 1) & 3)) << 4);
                ldmatrix_x4(afr[mi], addr);
            }
            uint32_t bfr[4][4];
#pragma unroll
            for (int nt = 0; nt < 4; nt++) {
                int krow  = kk * 16 + bl;
                int chunk = wn * 8 + nt * 2 + bh;
                uint32_t addr = sB + krow * 256 + ((chunk ^ (krow & 7)) << 4);
                ldmatrix_x4_trans(bfr[nt], addr);
            }
#pragma unroll
            for (int mi = 0; mi < 4; mi++)
#pragma unroll
                for (int nj = 0; nj < 8; nj++)
                    mma16816(acc[mi][nj], afr[mi],
                             bfr[nj >> 1][(nj & 1) * 2], bfr[nj >> 1][(nj & 1) * 2 + 1]);
        }
    }

    // Epilogue
#pragma unroll
    for (int mi = 0; mi < 4; mi++) {
#pragma unroll
        for (int half = 0; half < 2; half++) {
            int o = o0 + wm * 64 + mi * 16 + half * 8 + (lane >> 2);
            float bv;
            float* dst;
            if (mode == 0) {
                int c2 = o / 3;
                int j  = o - c2 * 3;
                bv = bias[g * 768 + o];
                if (j == 0)      dst = g_Q + ((size_t)bg * DIM_ + c2) * S_;
                else if (j == 1) dst = g_K + ((size_t)bg * DIM_ + c2) * SPAD;
                else             dst = g_V + ((size_t)bg * DIM_ + c2) * SPAD;
            } else {
                bv  = bias[g * 256 + o];
                dst = out + ((size_t)bg * 256 + o) * S_;
            }
            dst += t0 + wn * 64 + (lane & 3) * 2;
#pragma unroll
            for (int nj = 0; nj < 8; nj++) {
                float2 v;
                v.x = acc[mi][nj][half * 2 + 0] + bv;
                v.y = acc[mi][nj][half * 2 + 1] + bv;
                *reinterpret_cast<float2*>(dst + nj * 8) = v;
            }
        }
    }
}

// ---------------------------------------------------------------------------
// Fill K/V pad column t=4096 with bias
// ---------------------------------------------------------------------------
__global__ void fill_pad(const float* __restrict__ b_qkv) {
    int i = blockIdx.x * 256 + threadIdx.x;  // 32*256
    int bg = i >> 8, c2 = i & 255, g = bg & 7;
    g_K[((size_t)bg * DIM_ + c2) * SPAD + S_] = b_qkv[g * 768 + c2 * 3 + 1];
    g_V[((size_t)bg * DIM_ + c2) * SPAD + S_] = b_qkv[g * 768 + c2 * 3 + 2];
}

// ---------------------------------------------------------------------------
// Attention: one thread per (b, n, s). Writes attn_out fp32 and the attention
// output DIRECTLY as fp16 into g_Bo (pred GEMM's B operand).
// ---------------------------------------------------------------------------
__global__ __launch_bounds__(128)
void attn_kernel(float* __restrict__ attn_out) {
    const int s = blockIdx.x * 128 + threadIdx.x;
    const int n = blockIdx.y;
    const int b = blockIdx.z;

    float sc[8][16];
#pragma unroll
    for (int g = 0; g < 8; g++)
#pragma unroll
        for (int e = 0; e < 16; e++) sc[g][e] = 0.f;

    const size_t qbase = ((size_t)b * G_ * DIM_ + n * 32) * S_ + s;
    const size_t kbase = ((size_t)b * G_ * DIM_ + n * 32) * SPAD + s;

#pragma unroll 4
    for (int d = 0; d < 32; d++) {
        float qv[8], kv[16];
#pragma unroll
        for (int g = 0; g < 8; g++)
            qv[g] = g_Q[qbase + (size_t)(g * DIM_ + d) * S_];
#pragma unroll
        for (int e = 0; e < 8; e++) {
            size_t ko = kbase + (size_t)(e * DIM_ + d) * SPAD;
            kv[e]     = g_K[ko];
            kv[e + 8] = g_K[ko + 1];
        }
#pragma unroll
        for (int g = 0; g < 8; g++)
#pragma unroll
            for (int e = 0; e < 16; e++) sc[g][e] += qv[g] * kv[e];
    }

    const float scale = 0.17677669529663687f;  // 1/sqrt(32)
    const size_t abase = (size_t)(b * NH_ + n) * 128 * S_ + s;
#pragma unroll
    for (int g = 0; g < 8; g++) {
        float rs = 1e-9f;
#pragma unroll
        for (int e = 0; e < 16; e++) {
            float z = 1.f / (1.f + __expf(-sc[g][e] * scale));
            sc[g][e] = z;
            rs += z;
        }
        float inv = 1.f / rs;
#pragma unroll
        for (int e = 0; e < 16; e++) {
            sc[g][e] *= inv;
            attn_out[abase + (size_t)(g * 16 + e) * S_] = sc[g][e];
        }
    }

    // AV + direct fp16 write into g_Bo[bg][c], c = n*32+d
#pragma unroll 2
    for (int d = 0; d < 32; d++) {
        float vv[16];
#pragma unroll
        for (int e = 0; e < 8; e++) {
            size_t vo = kbase + (size_t)(e * DIM_ + d) * SPAD;
            vv[e]     = g_V[vo];
            vv[e + 8] = g_V[vo + 1];
        }
#pragma unroll
        for (int g = 0; g < 8; g++) {
            float a = 0.f;
#pragma unroll
            for (int e = 0; e < 16; e++) a += sc[g][e] * vv[e];
            g_Bo[((size_t)(b * 8 + g) * 256 + n * 32 + d) * S_ + s] = __float2half(a);
        }
    }
}

// ---------------------------------------------------------------------------
extern "C" void kernel_launch(void* const* d_in, const int* in_sizes, int n_in,
                              void* d_out, int out_size) {
    const float* x      = (const float*)d_in[0];
    const float* w_qkv  = (const float*)d_in[1];
    const float* b_qkv  = (const float*)d_in[2];
    const float* w_pred = (const float*)d_in[3];
    const float* b_pred = (const float*)d_in[4];

    float* pred = (float*)d_out;
    float* attn = pred + (size_t)B_ * HID_ * S_;

    void *pAq, *pAp, *pBx, *pBo;
    cudaGetSymbolAddress(&pAq, g_Aq);
    cudaGetSymbolAddress(&pAp, g_Ap);
    cudaGetSymbolAddress(&pBx, g_Bx);
    cudaGetSymbolAddress(&pBo, g_Bo);

    cudaFuncSetAttribute(gemm_mma, cudaFuncAttributeMaxDynamicSharedMemorySize, 65536);

    convert_w<<<(G_ * 768 * 256 + 255) / 256, 256>>>(w_qkv, (__half*)pAq, G_ * 768 * 256);
    convert_w<<<(G_ * 256 * 256 + 255) / 256, 256>>>(w_pred, (__half*)pAp, G_ * 256 * 256);
    convert_x<<<32 * 256 * 1024 / 256, 256>>>(x, (__half*)pBx);

    gemm_mma<<<dim3(32, 6, 32), 128, 65536>>>((const __half*)pAq,
                                              (const __half*)pBx,
                                              b_qkv, 768, 0, nullptr);
    fill_pad<<<32, 256>>>(b_qkv);

    attn_kernel<<<dim3(S_ / 128, NH_, B_), 128>>>(attn);

    gemm_mma<<<dim3(32, 2, 32), 128, 65536>>>((const __half*)pAp,
                                              (const __half*)pBo,
                                              b_pred, 256, 1, pred);
}

// round 9
// speedup vs baseline: 1.7483x; 1.0486x over previous
#include <cuda_runtime.h>
#include <cuda_fp16.h>
#include <cstdint>

// ---------------------------------------------------------------------------
// Problem constants
constexpr int B_   = 4;
constexpr int G_   = 8;
constexpr int NH_  = 8;
constexpr int DIM_ = 256;    // HID / G
constexpr int S_   = 4096;
constexpr int SPAD = 4104;   // padded K/V time pitch (S_+1, rounded to 8)
constexpr int HID_ = 2048;
constexpr int KP   = 256;    // K (plain fp16, single term)

// ---------------------------------------------------------------------------
// Scratch (device globals; allocation is forbidden) — ALL fp16 now
__device__ __half g_Q[(size_t)B_ * G_ * DIM_ * S_];    // (bg, c, s)
__device__ __half g_K[(size_t)B_ * G_ * DIM_ * SPAD];  // (bg, c, t) t in [0,4096]
__device__ __half g_V[(size_t)B_ * G_ * DIM_ * SPAD];

// B operands: [bg][256 rows][4096 t] fp16
__device__ __half g_Bx[(size_t)32 * 256 * S_];
__device__ __half g_Bo[(size_t)32 * 256 * S_];
__device__ __half g_Aq[(size_t)G_ * 768 * KP];  // w_qkv fp16 [g][o][c]
__device__ __half g_Ap[(size_t)G_ * 256 * KP];  // w_pred fp16

// ---------------------------------------------------------------------------
__device__ __forceinline__ uint32_t smem_u32(const void* p) {
    uint32_t a;
    asm("{ .reg .u64 t; cvta.to.shared.u64 t, %1; cvt.u32.u64 %0, t; }" : "=r"(a) : "l"(p));
    return a;
}
__device__ __forceinline__ void cp_async16(uint32_t dst, const void* src) {
    asm volatile("cp.async.cg.shared.global [%0], [%1], 16;" :: "r"(dst), "l"(src));
}
__device__ __forceinline__ void ldmatrix_x4(uint32_t* r, uint32_t addr) {
    asm volatile("ldmatrix.sync.aligned.m8n8.x4.shared.b16 {%0,%1,%2,%3}, [%4];"
                 : "=r"(r[0]), "=r"(r[1]), "=r"(r[2]), "=r"(r[3]) : "r"(addr));
}
__device__ __forceinline__ void ldmatrix_x4_trans(uint32_t* r, uint32_t addr) {
    asm volatile("ldmatrix.sync.aligned.m8n8.x4.trans.shared.b16 {%0,%1,%2,%3}, [%4];"
                 : "=r"(r[0]), "=r"(r[1]), "=r"(r[2]), "=r"(r[3]) : "r"(addr));
}
__device__ __forceinline__ void mma16816(float* c, const uint32_t* a, uint32_t b0, uint32_t b1) {
    asm volatile(
        "mma.sync.aligned.m16n8k16.row.col.f32.f16.f16.f32 "
        "{%0,%1,%2,%3}, {%4,%5,%6,%7}, {%8,%9}, {%0,%1,%2,%3};"
        : "+f"(c[0]), "+f"(c[1]), "+f"(c[2]), "+f"(c[3])
        : "r"(a[0]), "r"(a[1]), "r"(a[2]), "r"(a[3]), "r"(b0), "r"(b1));
}

// ---------------------------------------------------------------------------
// Weights [R][256] fp32 -> fp16
// ---------------------------------------------------------------------------
__global__ void convert_w(const float* __restrict__ w, __half* __restrict__ A,
                          int total) {
    int i = blockIdx.x * 256 + threadIdx.x;
    if (i >= total) return;
    A[i] = __float2half(w[i]);
}

// ---------------------------------------------------------------------------
// x fp32 -> g_Bx fp16 (elementwise)
// ---------------------------------------------------------------------------
__global__ __launch_bounds__(256)
void convert_x(const float* __restrict__ x, __half* __restrict__ dst) {
    int i = blockIdx.x * 256 + threadIdx.x;  // over 32*256*1024 float4 slots
    size_t base = (size_t)i << 2;
    float4 v = *reinterpret_cast<const float4*>(x + base);
    __half2 h0, h1;
    h0.x = __float2half(v.x); h0.y = __float2half(v.y);
    h1.x = __float2half(v.z); h1.y = __float2half(v.w);
    __half2* dh = reinterpret_cast<__half2*>(dst + base);
    dh[0] = h0; dh[1] = h1;
}

// ---------------------------------------------------------------------------
// mma.sync GEMM: D[128 o x 128 t] = A[o][k 256] . B[t][k 256]
// 4 warps, warp tile 64x64 (2m x 2n), BK=32, 4-stage cp.async, 1 barrier/chunk.
// mode 0: QKV scatter -> fp16 g_Q/g_K/g_V with bias; mode 1: pred fp32 out.
// ---------------------------------------------------------------------------
constexpr int NCH = 8;

__global__ __launch_bounds__(128, 2)
void gemm_mma(const __half* __restrict__ Aall,
              const __half* __restrict__ Ball,
              const float* __restrict__ bias,
              int Mtot, int mode, float* __restrict__ out) {
    // per stage: A 128(o)x32(k) 8KB (64B rows) + B 32(k)x128(t) 8KB (256B rows)
    extern __shared__ __align__(1024) char sbuf[];  // 4 * 16384
    const int tid  = threadIdx.x;
    const int lane = tid & 31;
    const int wid  = tid >> 5;
    const int wm   = wid & 1;   // m slice of 64
    const int wn   = wid >> 1;  // n slice of 64
    const int bg = blockIdx.z, g = bg & 7;
    const int o0 = blockIdx.y * 128, t0 = blockIdx.x * 128;

    const uint32_t sbase = smem_u32(sbuf);
    const __half* A  = Aall + ((size_t)g * Mtot + o0) * KP;
    const __half* Bp = Ball + (size_t)bg * 256 * S_;

    auto load_stage = [&](int ch, int st) {
        uint32_t sA = sbase + st * 16384;
        uint32_t sB = sA + 8192;
        const char* a8 = (const char*)A + (size_t)ch * 64;
        const char* b8 = (const char*)(Bp + ((size_t)ch * 32) * S_ + t0);
#pragma unroll
        for (int i = 0; i < 4; i++) {
            int id = tid + i * 128;
            int ra = id >> 2, ca = id & 3;
            uint32_t offA = ra * 64 + ((ca ^ ((ra >> 1) & 3)) << 4);
            cp_async16(sA + offA, a8 + (size_t)ra * (KP * 2) + ca * 16);
            int rb = id >> 4, cb = id & 15;
            uint32_t offB = rb * 256 + ((cb ^ (rb & 7)) << 4);
            cp_async16(sB + offB, b8 + (size_t)rb * (S_ * 2) + cb * 16);
        }
    };

    float acc[4][8][4];
#pragma unroll
    for (int mi = 0; mi < 4; mi++)
#pragma unroll
        for (int nj = 0; nj < 8; nj++)
#pragma unroll
            for (int q = 0; q < 4; q++) acc[mi][nj][q] = 0.f;

    load_stage(0, 0);
    asm volatile("cp.async.commit_group;" ::: "memory");
    load_stage(1, 1);
    asm volatile("cp.async.commit_group;" ::: "memory");
    load_stage(2, 2);
    asm volatile("cp.async.commit_group;" ::: "memory");

    const int gsel = lane >> 3;
    const int rin  = lane & 7;
    const int bl   = lane & 15;
    const int bh   = lane >> 4;

    for (int ch = 0; ch < NCH; ch++) {
        if (ch < NCH - 3) asm volatile("cp.async.wait_group 2;" ::: "memory");
        else              asm volatile("cp.async.wait_group 0;" ::: "memory");
        __syncthreads();
        if (ch + 3 < NCH) {
            load_stage(ch + 3, (ch + 3) & 3);
            asm volatile("cp.async.commit_group;" ::: "memory");
        }
        uint32_t sA = sbase + (ch & 3) * 16384;
        uint32_t sB = sA + 8192;
#pragma unroll
        for (int kk = 0; kk < 2; kk++) {
            uint32_t afr[4][4];
#pragma unroll
            for (int mi = 0; mi < 4; mi++) {
                int row   = wm * 64 + mi * 16 + (gsel & 1) * 8 + rin;
                int chunk = kk * 2 + (gsel >> 1);
                uint32_t addr = sA + row * 64 + ((chunk ^ ((row >> 1) & 3)) << 4);
                ldmatrix_x4(afr[mi], addr);
            }
            uint32_t bfr[4][4];
#pragma unroll
            for (int nt = 0; nt < 4; nt++) {
                int krow  = kk * 16 + bl;
                int chunk = wn * 8 + nt * 2 + bh;
                uint32_t addr = sB + krow * 256 + ((chunk ^ (krow & 7)) << 4);
                ldmatrix_x4_trans(bfr[nt], addr);
            }
#pragma unroll
            for (int mi = 0; mi < 4; mi++)
#pragma unroll
                for (int nj = 0; nj < 8; nj++)
                    mma16816(acc[mi][nj], afr[mi],
                             bfr[nj >> 1][(nj & 1) * 2], bfr[nj >> 1][(nj & 1) * 2 + 1]);
        }
    }

    // Epilogue
#pragma unroll
    for (int mi = 0; mi < 4; mi++) {
#pragma unroll
        for (int half = 0; half < 2; half++) {
            int o = o0 + wm * 64 + mi * 16 + half * 8 + (lane >> 2);
            if (mode == 0) {
                int c2 = o / 3;
                int j  = o - c2 * 3;
                float bv = bias[g * 768 + o];
                __half* dst;
                if (j == 0)      dst = g_Q + ((size_t)bg * DIM_ + c2) * S_;
                else if (j == 1) dst = g_K + ((size_t)bg * DIM_ + c2) * SPAD;
                else             dst = g_V + ((size_t)bg * DIM_ + c2) * SPAD;
                dst += t0 + wn * 64 + (lane & 3) * 2;
#pragma unroll
                for (int nj = 0; nj < 8; nj++) {
                    __half2 hv;
                    hv.x = __float2half(acc[mi][nj][half * 2 + 0] + bv);
                    hv.y = __float2half(acc[mi][nj][half * 2 + 1] + bv);
                    *reinterpret_cast<__half2*>(dst + nj * 8) = hv;
                }
            } else {
                float bv = bias[g * 256 + o];
                float* dst = out + ((size_t)bg * 256 + o) * S_
                           + t0 + wn * 64 + (lane & 3) * 2;
#pragma unroll
                for (int nj = 0; nj < 8; nj++) {
                    float2 v;
                    v.x = acc[mi][nj][half * 2 + 0] + bv;
                    v.y = acc[mi][nj][half * 2 + 1] + bv;
                    *reinterpret_cast<float2*>(dst + nj * 8) = v;
                }
            }
        }
    }
}

// ---------------------------------------------------------------------------
// Fill K/V pad column t=4096 with bias
// ---------------------------------------------------------------------------
__global__ void fill_pad(const float* __restrict__ b_qkv) {
    int i = blockIdx.x * 256 + threadIdx.x;  // 32*256
    int bg = i >> 8, c2 = i & 255, g = bg & 7;
    g_K[((size_t)bg * DIM_ + c2) * SPAD + S_] = __float2half(b_qkv[g * 768 + c2 * 3 + 1]);
    g_V[((size_t)bg * DIM_ + c2) * SPAD + S_] = __float2half(b_qkv[g * 768 + c2 * 3 + 2]);
}

// ---------------------------------------------------------------------------
// Attention: one thread per (b, n, s). fp16 Q/K/V in, fp32 math,
// attn_out fp32, attention output fp16 straight into g_Bo.
// ---------------------------------------------------------------------------
__global__ __launch_bounds__(128)
void attn_kernel(float* __restrict__ attn_out) {
    const int s = blockIdx.x * 128 + threadIdx.x;
    const int n = blockIdx.y;
    const int b = blockIdx.z;

    float sc[8][16];
#pragma unroll
    for (int g = 0; g < 8; g++)
#pragma unroll
        for (int e = 0; e < 16; e++) sc[g][e] = 0.f;

    const size_t qbase = ((size_t)b * G_ * DIM_ + n * 32) * S_ + s;
    const size_t kbase = ((size_t)b * G_ * DIM_ + n * 32) * SPAD + s;

#pragma unroll 4
    for (int d = 0; d < 32; d++) {
        float qv[8], kv[16];
#pragma unroll
        for (int g = 0; g < 8; g++)
            qv[g] = __half2float(g_Q[qbase + (size_t)(g * DIM_ + d) * S_]);
#pragma unroll
        for (int e = 0; e < 8; e++) {
            size_t ko = kbase + (size_t)(e * DIM_ + d) * SPAD;
            kv[e]     = __half2float(g_K[ko]);
            kv[e + 8] = __half2float(g_K[ko + 1]);
        }
#pragma unroll
        for (int g = 0; g < 8; g++)
#pragma unroll
            for (int e = 0; e < 16; e++) sc[g][e] += qv[g] * kv[e];
    }

    const float scale = 0.17677669529663687f;  // 1/sqrt(32)
    const size_t abase = (size_t)(b * NH_ + n) * 128 * S_ + s;
#pragma unroll
    for (int g = 0; g < 8; g++) {
        float rs = 1e-9f;
#pragma unroll
        for (int e = 0; e < 16; e++) {
            float z = 1.f / (1.f + __expf(-sc[g][e] * scale));
            sc[g][e] = z;
            rs += z;
        }
        float inv = 1.f / rs;
#pragma unroll
        for (int e = 0; e < 16; e++) {
            sc[g][e] *= inv;
            attn_out[abase + (size_t)(g * 16 + e) * S_] = sc[g][e];
        }
    }

    // AV + direct fp16 write into g_Bo[bg][c], c = n*32+d
#pragma unroll 2
    for (int d = 0; d < 32; d++) {
        float vv[16];
#pragma unroll
        for (int e = 0; e < 8; e++) {
            size_t vo = kbase + (size_t)(e * DIM_ + d) * SPAD;
            vv[e]     = __half2float(g_V[vo]);
            vv[e + 8] = __half2float(g_V[vo + 1]);
        }
#pragma unroll
        for (int g = 0; g < 8; g++) {
            float a = 0.f;
#pragma unroll
            for (int e = 0; e < 16; e++) a += sc[g][e] * vv[e];
            g_Bo[((size_t)(b * 8 + g) * 256 + n * 32 + d) * S_ + s] = __float2half(a);
        }
    }
}

// ---------------------------------------------------------------------------
extern "C" void kernel_launch(void* const* d_in, const int* in_sizes, int n_in,
                              void* d_out, int out_size) {
    const float* x      = (const float*)d_in[0];
    const float* w_qkv  = (const float*)d_in[1];
    const float* b_qkv  = (const float*)d_in[2];
    const float* w_pred = (const float*)d_in[3];
    const float* b_pred = (const float*)d_in[4];

    float* pred = (float*)d_out;
    float* attn = pred + (size_t)B_ * HID_ * S_;

    void *pAq, *pAp, *pBx, *pBo;
    cudaGetSymbolAddress(&pAq, g_Aq);
    cudaGetSymbolAddress(&pAp, g_Ap);
    cudaGetSymbolAddress(&pBx, g_Bx);
    cudaGetSymbolAddress(&pBo, g_Bo);

    cudaFuncSetAttribute(gemm_mma, cudaFuncAttributeMaxDynamicSharedMemorySize, 65536);

    convert_w<<<(G_ * 768 * 256 + 255) / 256, 256>>>(w_qkv, (__half*)pAq, G_ * 768 * 256);
    convert_w<<<(G_ * 256 * 256 + 255) / 256, 256>>>(w_pred, (__half*)pAp, G_ * 256 * 256);
    convert_x<<<32 * 256 * 1024 / 256, 256>>>(x, (__half*)pBx);

    gemm_mma<<<dim3(32, 6, 32), 128, 65536>>>((const __half*)pAq,
                                              (const __half*)pBx,
                                              b_qkv, 768, 0, nullptr);
    fill_pad<<<32, 256>>>(b_qkv);

    attn_kernel<<<dim3(S_ / 128, NH_, B_), 128>>>(attn);

    gemm_mma<<<dim3(32, 2, 32), 128, 65536>>>((const __half*)pAp,
                                              (const __half*)pBo,
                                              b_pred, 256, 1, pred);
}